// round 2
// baseline (speedup 1.0000x reference)
#include <cuda_runtime.h>
#include <cstdint>

#define N_NODES 50000
#define DFEAT 128
#define MAX_E 800000
#define GEMM_ROWS 64
#define GEMM_SMEM ((DFEAT*DFEAT + GEMM_ROWS*DFEAT) * 4)  // 64KB W + 32KB X tile

// ---- scratch (static device globals: allocation-free) ----
__device__ float g_hs[N_NODES * DFEAT];    // (X@W) * dinv[row]
__device__ float g_buf[N_NODES * DFEAT];   // layer-1 output / layer-2 input
__device__ float g_dinv[N_NODES];
__device__ int   g_cnt[N_NODES];
__device__ int   g_cursor[N_NODES];
__device__ int   g_rowptr[N_NODES + 1];
__device__ int   g_csr[MAX_E];

// ---------------- graph build ----------------
__global__ void zero_counters() {
    int i = blockIdx.x * blockDim.x + threadIdx.x;
    if (i < N_NODES) { g_cnt[i] = 0; g_cursor[i] = 0; }
}

__global__ void count_deg(const int* __restrict__ dst, int E) {
    int e = blockIdx.x * blockDim.x + threadIdx.x;
    if (e < E) atomicAdd(&g_cnt[dst[e]], 1);
}

// single-block exclusive scan over 50000 counts; also computes dinv = rsqrt(deg+1)
__global__ void scan_deg(int E) {
    __shared__ int part[1024];
    int t = threadIdx.x;
    const int C = (N_NODES + 1023) / 1024;   // 49
    int lo = t * C;
    int hi = min(lo + C, N_NODES);
    int s = 0;
    for (int i = lo; i < hi; i++) s += g_cnt[i];
    part[t] = s;
    __syncthreads();
    for (int off = 1; off < 1024; off <<= 1) {
        int v = (t >= off) ? part[t - off] : 0;
        __syncthreads();
        part[t] += v;
        __syncthreads();
    }
    int run = (t > 0) ? part[t - 1] : 0;
    for (int i = lo; i < hi; i++) {
        g_rowptr[i] = run;
        int c = g_cnt[i];
        run += c;
        g_dinv[i] = rsqrtf((float)c + 1.0f);
    }
    if (t == 0) g_rowptr[N_NODES] = E;
}

__global__ void fill_csr(const int* __restrict__ src,
                         const int* __restrict__ dst, int E) {
    int e = blockIdx.x * blockDim.x + threadIdx.x;
    if (e < E) {
        int d = dst[e];
        int pos = atomicAdd(&g_cursor[d], 1);
        g_csr[g_rowptr[d] + pos] = src[e];
    }
}

// ---------------- GEMM: out[row] = (X[row] @ W) * dinv[row] ----------------
// block = 256 threads, 64 rows per block, full 128x128 W in smem.
// warp w handles rows w*8 .. w*8+7; lane handles 4 columns (float4).
__global__ void gemm_scale(const float* __restrict__ X, const float* __restrict__ W,
                           float* __restrict__ out, int nrows) {
    extern __shared__ float sm[];
    float* Ws = sm;                       // 128*128
    float* Xs = sm + DFEAT * DFEAT;       // 64*128
    int tid = threadIdx.x;

    float4* Ws4 = (float4*)Ws;
    const float4* W4 = (const float4*)W;
    for (int i = tid; i < DFEAT * DFEAT / 4; i += 256) Ws4[i] = W4[i];

    int row0 = blockIdx.x * GEMM_ROWS;
    int nr = min(GEMM_ROWS, nrows - row0);
    float4* Xs4 = (float4*)Xs;
    const float4* X4 = (const float4*)(X + (size_t)row0 * DFEAT);
    for (int i = tid; i < nr * 32; i += 256) Xs4[i] = X4[i];
    for (int i = nr * 32 + tid; i < GEMM_ROWS * 32; i += 256)
        Xs4[i] = make_float4(0.f, 0.f, 0.f, 0.f);
    __syncthreads();

    int warp = tid >> 5, lane = tid & 31;
    float4 acc[8];
#pragma unroll
    for (int r = 0; r < 8; r++) acc[r] = make_float4(0.f, 0.f, 0.f, 0.f);

    for (int k = 0; k < DFEAT; k++) {
        float4 w4 = Ws4[k * 32 + lane];
#pragma unroll
        for (int r = 0; r < 8; r++) {
            float xv = Xs[(warp * 8 + r) * DFEAT + k];   // broadcast within warp
            acc[r].x = fmaf(xv, w4.x, acc[r].x);
            acc[r].y = fmaf(xv, w4.y, acc[r].y);
            acc[r].z = fmaf(xv, w4.z, acc[r].z);
            acc[r].w = fmaf(xv, w4.w, acc[r].w);
        }
    }

#pragma unroll
    for (int r = 0; r < 8; r++) {
        int row = warp * 8 + r;
        if (row < nr) {
            float dsc = g_dinv[row0 + row];
            float4 v;
            v.x = acc[r].x * dsc; v.y = acc[r].y * dsc;
            v.z = acc[r].z * dsc; v.w = acc[r].w * dsc;
            ((float4*)out)[(size_t)(row0 + row) * 32 + lane] = v;
        }
    }
}

// ---------------- aggregation: out = relu(dinv[n]*(hs[n] + sum hs[src]) + b) ----------------
// one warp per node; lane owns 4 features (float4). CSR gather, no float atomics.
__global__ void aggregate_relu(const float* __restrict__ hs,
                               const float* __restrict__ bias,
                               float* __restrict__ out) {
    int gw = (blockIdx.x * blockDim.x + threadIdx.x) >> 5;
    int lane = threadIdx.x & 31;
    if (gw >= N_NODES) return;
    const float4* hs4 = (const float4*)hs;
    float4 acc = hs4[(size_t)gw * 32 + lane];   // self-loop term (already dinv-scaled)
    int e0 = g_rowptr[gw], e1 = g_rowptr[gw + 1];
    for (int e = e0; e < e1; e++) {
        int s = g_csr[e];                       // broadcast load across warp
        float4 v = hs4[(size_t)s * 32 + lane];
        acc.x += v.x; acc.y += v.y; acc.z += v.z; acc.w += v.w;
    }
    float d = g_dinv[gw];
    float4 b = ((const float4*)bias)[lane];
    float4 r;
    r.x = fmaxf(fmaf(acc.x, d, b.x), 0.f);
    r.y = fmaxf(fmaf(acc.y, d, b.y), 0.f);
    r.z = fmaxf(fmaf(acc.z, d, b.z), 0.f);
    r.w = fmaxf(fmaf(acc.w, d, b.w), 0.f);
    ((float4*)out)[(size_t)gw * 32 + lane] = r;
}

// layer-2 aggregation fused with the final 128->1 projection
__global__ void aggregate_final(const float* __restrict__ hs,
                                const float* __restrict__ bias,
                                const float* __restrict__ Wl,
                                const float* __restrict__ bl,
                                float* __restrict__ out) {
    int gw = (blockIdx.x * blockDim.x + threadIdx.x) >> 5;
    int lane = threadIdx.x & 31;
    if (gw >= N_NODES) return;
    const float4* hs4 = (const float4*)hs;
    float4 acc = hs4[(size_t)gw * 32 + lane];
    int e0 = g_rowptr[gw], e1 = g_rowptr[gw + 1];
    for (int e = e0; e < e1; e++) {
        int s = g_csr[e];
        float4 v = hs4[(size_t)s * 32 + lane];
        acc.x += v.x; acc.y += v.y; acc.z += v.z; acc.w += v.w;
    }
    float d = g_dinv[gw];
    float4 b = ((const float4*)bias)[lane];
    float4 r;
    r.x = fmaxf(fmaf(acc.x, d, b.x), 0.f);
    r.y = fmaxf(fmaf(acc.y, d, b.y), 0.f);
    r.z = fmaxf(fmaf(acc.z, d, b.z), 0.f);
    r.w = fmaxf(fmaf(acc.w, d, b.w), 0.f);
    float4 wl = ((const float4*)Wl)[lane];
    float dot = r.x * wl.x + r.y * wl.y + r.z * wl.z + r.w * wl.w;
#pragma unroll
    for (int off = 16; off; off >>= 1)
        dot += __shfl_xor_sync(0xFFFFFFFFu, dot, off);
    if (lane == 0) out[gw] = dot + bl[0];
}

// ---------------- launch ----------------
extern "C" void kernel_launch(void* const* d_in, const int* in_sizes, int n_in,
                              void* d_out, int out_size) {
    const float* x  = (const float*)d_in[0];
    const int*   ei = (const int*)d_in[1];    // JAX default x64-disabled -> int32!
    const float* W1 = (const float*)d_in[2];
    const float* b1 = (const float*)d_in[3];
    const float* W2 = (const float*)d_in[4];
    const float* b2 = (const float*)d_in[5];
    const float* Wl = (const float*)d_in[6];
    const float* bl = (const float*)d_in[7];
    float* out = (float*)d_out;

    int E = in_sizes[1] / 2;
    const int* src = ei;
    const int* dst = ei + E;

    void *p_hs, *p_buf;
    cudaGetSymbolAddress(&p_hs, g_hs);
    cudaGetSymbolAddress(&p_buf, g_buf);
    float* hs = (float*)p_hs;
    float* buf = (float*)p_buf;

    cudaFuncSetAttribute(gemm_scale,
                         cudaFuncAttributeMaxDynamicSharedMemorySize, GEMM_SMEM);

    // graph build (per call: edge_index is a runtime input)
    zero_counters<<<(N_NODES + 255) / 256, 256>>>();
    count_deg<<<(E + 255) / 256, 256>>>(dst, E);
    scan_deg<<<1, 1024>>>(E);
    fill_csr<<<(E + 255) / 256, 256>>>(src, dst, E);

    int gemm_grid = (N_NODES + GEMM_ROWS - 1) / GEMM_ROWS;
    int agg_grid  = (N_NODES + 7) / 8;   // 8 warps per 256-thread block

    // layer 1
    gemm_scale<<<gemm_grid, 256, GEMM_SMEM>>>(x, W1, hs, N_NODES);
    aggregate_relu<<<agg_grid, 256>>>(hs, b1, buf);
    // layer 2 + fused final projection
    gemm_scale<<<gemm_grid, 256, GEMM_SMEM>>>(buf, W2, hs, N_NODES);
    aggregate_final<<<agg_grid, 256>>>(hs, b2, Wl, bl, out);
}